// round 1
// baseline (speedup 1.0000x reference)
#include <cuda_runtime.h>
#include <cstdint>

// ============================================================================
// EGNN decoder layer, fused fp32 implementation.
//   N=50000 nodes, E=600000 edges, D=128.
// Kernel 1: zero scratch accumulators.
// Kernel 2: per-64-edge tile: gather [h[row],h[col],dist2], 3 GEMMs in SMEM,
//           float4-atomic scatter of messages (agg) and coord weights.
// Kernel 3: node MLP: h_new = relu([h,agg]@Wn1+bn1)@Wn2+bn2 ; coords+coordU.
// Output layout: [ h_new (N*128 floats) | coords_new (N*3 floats) ].
// ============================================================================

#define TPB 256
#define BE  64

#define MAXN 50000
static __device__ float g_agg[MAXN * 128];
static __device__ float g_coordU[MAXN * 3];

// SMEM layout (floats). Strides padded to kill bank conflicts on A reads.
#define LDA 260   // stride for 256-wide A buffers
#define LDH 132   // stride for 128-wide buffers
#define SA_FLOATS (64 * 260)   // 16640
#define SH_FLOATS (64 * 132)   // 8448
#define SB_FLOATS (16 * 128)   // 2048
// extras: rel(192) dist(64) cw(64) floats + row(64) col(64) ints
#define SMEM_BYTES ((SA_FLOATS + SH_FLOATS + SB_FLOATS + 192 + 64 + 64) * 4 + 128 * 4)

#define FMA_ROW(i, a)                                                          \
  acc[i][0] += (a) * b0.x; acc[i][1] += (a) * b0.y;                            \
  acc[i][2] += (a) * b0.z; acc[i][3] += (a) * b0.w;                            \
  acc[i][4] += (a) * b1.x; acc[i][5] += (a) * b1.y;                            \
  acc[i][6] += (a) * b1.z; acc[i][7] += (a) * b1.w;

// C[64][128] += A[64][K](smem, stride LDAv) * B[K][128](global, L2-hot).
// 256 threads: 16x16 grid, each computes a 4x8 micro-tile.
template <int K, int LDAv>
__device__ __forceinline__ void gemm_chunked(const float* __restrict__ sAa,
                                             const float* __restrict__ gB,
                                             float* __restrict__ sB,
                                             float (&acc)[4][8],
                                             int tr, int tc, int tid) {
  for (int kb = 0; kb < K; kb += 16) {
    __syncthreads();
    // stage B chunk: 16x128 floats = 512 float4, 2 per thread, coalesced
#pragma unroll
    for (int ii = 0; ii < 2; ii++) {
      int i = tid + ii * 256;
      int krow = i >> 5;
      int c4 = i & 31;
      *(float4*)&sB[krow * 128 + c4 * 4] =
          *(const float4*)&gB[(long long)(kb + krow) * 128 + c4 * 4];
    }
    __syncthreads();
#pragma unroll
    for (int k = 0; k < 16; k++) {
      const float* ap = sAa + kb + k;
      float a0 = ap[(tr * 4 + 0) * LDAv];
      float a1 = ap[(tr * 4 + 1) * LDAv];
      float a2 = ap[(tr * 4 + 2) * LDAv];
      float a3 = ap[(tr * 4 + 3) * LDAv];
      float4 b0 = *(const float4*)&sB[k * 128 + tc * 8];
      float4 b1 = *(const float4*)&sB[k * 128 + tc * 8 + 4];
      FMA_ROW(0, a0)
      FMA_ROW(1, a1)
      FMA_ROW(2, a2)
      FMA_ROW(3, a3)
    }
  }
}

__global__ void egnn_zero_kernel(int N) {
  long long total = (long long)N * 131;
  long long stride = (long long)gridDim.x * blockDim.x;
  long long n128 = (long long)N * 128;
  for (long long i = (long long)blockIdx.x * blockDim.x + threadIdx.x; i < total; i += stride) {
    if (i < n128) g_agg[i] = 0.f;
    else g_coordU[i - n128] = 0.f;
  }
}

__global__ void __launch_bounds__(256, 2)
egnn_edge_kernel(const float* __restrict__ h,
                 const float* __restrict__ coords,
                 const void* __restrict__ eidx_raw,
                 const float* __restrict__ We1, const float* __restrict__ be1,
                 const float* __restrict__ We2, const float* __restrict__ be2,
                 const float* __restrict__ Wc1, const float* __restrict__ bc1,
                 const float* __restrict__ Wc2,
                 int N, long long E) {
  extern __shared__ float smem[];
  float* sA = smem;                     // ef [64][256] (LDA) ; later messages [64][128] (LDH)
  float* sH = sA + SA_FLOATS;           // hidden / t2 [64][128] (LDH)
  float* sB = sH + SH_FLOATS;           // weight chunk [16][128]
  float* sRel = sB + SB_FLOATS;         // [64][3]
  float* sDist = sRel + 192;            // [64]
  float* sCW = sDist + 64;              // [64]
  int* sRow = (int*)(sCW + 64);         // [64]
  int* sCol = sRow + 64;                // [64]

  int tid = threadIdx.x;
  int tr = tid >> 4;
  int tc = tid & 15;
  long long e0 = (long long)blockIdx.x * BE;

  // --- phase 0: indices, rel coords, dist2 ---
  if (tid < BE) {
    long long e = e0 + tid;
    int r = -1, c = 0;
    float rx = 0.f, ry = 0.f, rz = 0.f;
    if (e < E) {
      // dtype sniff: int64 edge_index has zero high-words at odd 32-bit slots
      const unsigned* w = (const unsigned*)eidx_raw;
      bool is64 = (w[1] == 0u && w[3] == 0u && w[5] == 0u && w[7] == 0u);
      if (is64) {
        r = (int)((const long long*)eidx_raw)[e];
        c = (int)((const long long*)eidx_raw)[E + e];
      } else {
        r = ((const int*)eidx_raw)[e];
        c = ((const int*)eidx_raw)[E + e];
      }
      rx = coords[(long long)r * 3 + 0] - coords[(long long)c * 3 + 0];
      ry = coords[(long long)r * 3 + 1] - coords[(long long)c * 3 + 1];
      rz = coords[(long long)r * 3 + 2] - coords[(long long)c * 3 + 2];
    }
    sRow[tid] = r;
    sCol[tid] = c;
    sRel[tid * 3 + 0] = rx;
    sRel[tid * 3 + 1] = ry;
    sRel[tid * 3 + 2] = rz;
    sDist[tid] = rx * rx + ry * ry + rz * rz;
  }
  __syncthreads();

  // --- phase 1: gather h[row] | h[col] into sA (64 x 256, stride LDA) ---
#pragma unroll
  for (int ii = 0; ii < 16; ii++) {
    int i = tid + ii * 256;     // 64 edges * 64 float4
    int le = i >> 6;
    int q = i & 63;
    int r = sRow[le];
    float4 v = make_float4(0.f, 0.f, 0.f, 0.f);
    if (r >= 0) {
      const float* src = (q < 32)
          ? &h[(long long)r * 128 + q * 4]
          : &h[(long long)sCol[le] * 128 + (q - 32) * 4];
      v = *(const float4*)src;
    }
    *(float4*)&sA[le * LDA + q * 4] = v;
  }
  // (gemm's leading __syncthreads orders the gather)

  float acc[4][8];

  // --- GEMM1: hidden = relu(ef @ We1 + be1), ef includes dist2 column 256 ---
  {
    const float* we1_last = We1 + 256 * 128;
#pragma unroll
    for (int i = 0; i < 4; i++) {
      float d = sDist[tr * 4 + i];
#pragma unroll
      for (int j = 0; j < 8; j++)
        acc[i][j] = be1[tc * 8 + j] + d * we1_last[tc * 8 + j];
    }
  }
  gemm_chunked<256, LDA>(sA, We1, sB, acc, tr, tc, tid);
#pragma unroll
  for (int i = 0; i < 4; i++)
#pragma unroll
    for (int j = 0; j < 8; j++)
      sH[(tr * 4 + i) * LDH + tc * 8 + j] = fmaxf(acc[i][j], 0.f);

  // --- GEMM2: messages = hidden @ We2 + be2 ---
#pragma unroll
  for (int i = 0; i < 4; i++)
#pragma unroll
    for (int j = 0; j < 8; j++) acc[i][j] = be2[tc * 8 + j];
  gemm_chunked<128, LDH>(sH, We2, sB, acc, tr, tc, tid);
  float* sM = sA;  // messages live in the (now dead) ef region, stride LDH
#pragma unroll
  for (int i = 0; i < 4; i++)
#pragma unroll
    for (int j = 0; j < 8; j++)
      sM[(tr * 4 + i) * LDH + tc * 8 + j] = acc[i][j];

  // --- GEMM3: t2 = relu(messages @ Wc1 + bc1)  (leading sync orders sM) ---
#pragma unroll
  for (int i = 0; i < 4; i++)
#pragma unroll
    for (int j = 0; j < 8; j++) acc[i][j] = bc1[tc * 8 + j];
  gemm_chunked<128, LDH>(sM, Wc1, sB, acc, tr, tc, tid);
#pragma unroll
  for (int i = 0; i < 4; i++)
#pragma unroll
    for (int j = 0; j < 8; j++)
      sH[(tr * 4 + i) * LDH + tc * 8 + j] = fmaxf(acc[i][j], 0.f);
  __syncthreads();

  // --- coord weights: cw = t2 @ Wc2  (4 threads per edge row) ---
  {
    int r = tid >> 2;
    int q = tid & 3;
    float s = 0.f;
    const float* t2row = &sH[r * LDH + q * 32];
    const float* w2 = &Wc2[q * 32];
#pragma unroll
    for (int d = 0; d < 32; d++) s += t2row[d] * w2[d];
    s += __shfl_xor_sync(0xffffffffu, s, 1);
    s += __shfl_xor_sync(0xffffffffu, s, 2);
    if (q == 0) sCW[r] = s;
  }
  __syncthreads();

  // --- epilogue: float4 atomic scatter of messages; scalar for coords ---
#pragma unroll
  for (int ii = 0; ii < 8; ii++) {
    int i = tid + ii * 256;     // 64 * 32 float4
    int le = i >> 5;
    int c4 = i & 31;
    int r = sRow[le];
    if (r >= 0) {
      float4 v = *(float4*)&sM[le * LDH + c4 * 4];
      atomicAdd((float4*)&g_agg[(long long)r * 128 + c4 * 4], v);
    }
  }
  if (tid < 192) {
    int le = tid / 3;
    int a = tid - le * 3;
    int r = sRow[le];
    if (r >= 0)
      atomicAdd(&g_coordU[(long long)r * 3 + a], sCW[le] * sRel[le * 3 + a]);
  }
}

__global__ void __launch_bounds__(256, 2)
egnn_node_kernel(const float* __restrict__ h,
                 const float* __restrict__ coords,
                 const float* __restrict__ Wn1, const float* __restrict__ bn1,
                 const float* __restrict__ Wn2, const float* __restrict__ bn2,
                 float* __restrict__ out, int N) {
  extern __shared__ float smem[];
  float* sA = smem;
  float* sH = sA + SA_FLOATS;
  float* sB = sH + SH_FLOATS;

  int tid = threadIdx.x;
  int tr = tid >> 4;
  int tc = tid & 15;
  int n0 = blockIdx.x * 64;

  // load A = [h[n] | agg[n]]
#pragma unroll
  for (int ii = 0; ii < 16; ii++) {
    int i = tid + ii * 256;
    int ln = i >> 6;
    int q = i & 63;
    int n = n0 + ln;
    float4 v = make_float4(0.f, 0.f, 0.f, 0.f);
    if (n < N) {
      v = (q < 32) ? *(const float4*)&h[(long long)n * 128 + q * 4]
                   : *(const float4*)&g_agg[(long long)n * 128 + (q - 32) * 4];
    }
    *(float4*)&sA[ln * LDA + q * 4] = v;
  }

  float acc[4][8];
#pragma unroll
  for (int i = 0; i < 4; i++)
#pragma unroll
    for (int j = 0; j < 8; j++) acc[i][j] = bn1[tc * 8 + j];
  gemm_chunked<256, LDA>(sA, Wn1, sB, acc, tr, tc, tid);
#pragma unroll
  for (int i = 0; i < 4; i++)
#pragma unroll
    for (int j = 0; j < 8; j++)
      sH[(tr * 4 + i) * LDH + tc * 8 + j] = fmaxf(acc[i][j], 0.f);

#pragma unroll
  for (int i = 0; i < 4; i++)
#pragma unroll
    for (int j = 0; j < 8; j++) acc[i][j] = bn2[tc * 8 + j];
  gemm_chunked<128, LDH>(sH, Wn2, sB, acc, tr, tc, tid);

  // write h_new
#pragma unroll
  for (int i = 0; i < 4; i++) {
    int n = n0 + tr * 4 + i;
    if (n < N) {
      float4 v0 = make_float4(acc[i][0], acc[i][1], acc[i][2], acc[i][3]);
      float4 v1 = make_float4(acc[i][4], acc[i][5], acc[i][6], acc[i][7]);
      *(float4*)&out[(long long)n * 128 + tc * 8] = v0;
      *(float4*)&out[(long long)n * 128 + tc * 8 + 4] = v1;
    }
  }
  // write coords_new
  for (int i = tid; i < 64 * 3; i += 256) {
    int ln = i / 3;
    int a = i - ln * 3;
    int n = n0 + ln;
    if (n < N)
      out[(long long)N * 128 + (long long)n * 3 + a] =
          coords[(long long)n * 3 + a] + g_coordU[(long long)n * 3 + a];
  }
}

extern "C" void kernel_launch(void* const* d_in, const int* in_sizes, int n_in,
                              void* d_out, int out_size) {
  const float* h      = (const float*)d_in[0];
  const float* coords = (const float*)d_in[1];
  const void*  eidx   = d_in[2];
  const float* We1 = (const float*)d_in[3];
  const float* be1 = (const float*)d_in[4];
  const float* We2 = (const float*)d_in[5];
  const float* be2 = (const float*)d_in[6];
  const float* Wn1 = (const float*)d_in[7];
  const float* bn1 = (const float*)d_in[8];
  const float* Wn2 = (const float*)d_in[9];
  const float* bn2 = (const float*)d_in[10];
  const float* Wc1 = (const float*)d_in[11];
  const float* bc1 = (const float*)d_in[12];
  const float* Wc2 = (const float*)d_in[13];

  int N = in_sizes[0] / 128;
  long long E = (long long)in_sizes[2] / 2;

  cudaFuncSetAttribute(egnn_edge_kernel,
                       cudaFuncAttributeMaxDynamicSharedMemorySize, SMEM_BYTES);
  cudaFuncSetAttribute(egnn_node_kernel,
                       cudaFuncAttributeMaxDynamicSharedMemorySize, SMEM_BYTES);

  egnn_zero_kernel<<<432, 256>>>(N);
  int egrid = (int)((E + BE - 1) / BE);
  egnn_edge_kernel<<<egrid, 256, SMEM_BYTES>>>(h, coords, eidx,
                                               We1, be1, We2, be2,
                                               Wc1, bc1, Wc2, N, E);
  int ngrid = (N + 63) / 64;
  egnn_node_kernel<<<ngrid, 256, SMEM_BYTES>>>(h, coords, Wn1, bn1, Wn2, bn2,
                                               (float*)d_out, N);
}

// round 3
// speedup vs baseline: 3.4609x; 3.4609x over previous
#include <cuda_runtime.h>
#include <cuda_bf16.h>
#include <cstdint>

// ============================================================================
// EGNN decoder layer — warp-level HMMA (mma.sync m16n8k16 bf16) with
// split-precision: X = Xhi + Xlo (bf16);  X@W ~= Xhi@Whi + Xhi@Wlo + Xlo@Whi,
// fp32 accumulation. Target sm_100 (no tcgen05 — harness compiles non-'a').
// Weights pre-packed into mma B-fragment layout by a prep kernel.
// ============================================================================

#define MAXN 50000
static __device__ float g_agg[MAXN * 128];
static __device__ float g_coordU[MAXN * 3];

// B-fragment images, hi and lo. u32 layout: ((t*16 + j)*32 + lane)*2 + r
//  t = kstep (16 rows of K), j = n8 tile (0..15), r selects k-offset 0/8.
//  u32 packs (W[k][n], W[k+1][n]) as bf16 pair, n = j*8 + lane/4,
//  k = t*16 + (lane%4)*2 + r*8.
#define WB_WE1 0        // K=256 -> 16384 u32
#define WB_WE2 16384    // K=128 ->  8192
#define WB_WC1 24576    //           8192
#define WB_WN1 32768    // K=256 -> 16384
#define WB_WN2 49152    //           8192
#define WB_TOTAL 57344
static __device__ __align__(16) uint32_t g_Bh[WB_TOTAL];
static __device__ __align__(16) uint32_t g_Bl[WB_TOTAL];
static __device__ float g_w256[128];  // dist2 row (row 256) of We1

// ---------------------------------------------------------------------------
__device__ __forceinline__ uint32_t smem_u32(const void* p) {
  uint32_t a;
  asm("{ .reg .u64 t; cvta.to.shared.u64 t, %1; cvt.u32.u64 %0, t; }"
      : "=r"(a) : "l"(p));
  return a;
}

__device__ __forceinline__ void ldm4(uint32_t* r, uint32_t addr) {
  asm volatile("ldmatrix.sync.aligned.m8n8.x4.shared.b16 {%0,%1,%2,%3}, [%4];"
               : "=r"(r[0]), "=r"(r[1]), "=r"(r[2]), "=r"(r[3]) : "r"(addr));
}

__device__ __forceinline__ void mma16816(float* c, const uint32_t* a, uint2 b) {
  asm volatile(
      "mma.sync.aligned.m16n8k16.row.col.f32.bf16.bf16.f32 "
      "{%0,%1,%2,%3}, {%4,%5,%6,%7}, {%8,%9}, {%0,%1,%2,%3};"
      : "+f"(c[0]), "+f"(c[1]), "+f"(c[2]), "+f"(c[3])
      : "r"(a[0]), "r"(a[1]), "r"(a[2]), "r"(a[3]), "r"(b.x), "r"(b.y));
}

__device__ __forceinline__ void red_v2(float* g, float x, float y) {
  asm volatile("red.global.add.v2.f32 [%0], {%1,%2};"
               :: "l"(g), "f"(x), "f"(y) : "memory");
}

__device__ __forceinline__ uint32_t pack_hi(float a, float b) {
  __nv_bfloat16 x = __float2bfloat16_rn(a), y = __float2bfloat16_rn(b);
  return (uint32_t)__bfloat16_as_ushort(x) | ((uint32_t)__bfloat16_as_ushort(y) << 16);
}
__device__ __forceinline__ void split2(float a, float b, uint32_t& hi, uint32_t& lo) {
  __nv_bfloat16 ah = __float2bfloat16_rn(a), bh = __float2bfloat16_rn(b);
  hi = (uint32_t)__bfloat16_as_ushort(ah) | ((uint32_t)__bfloat16_as_ushort(bh) << 16);
  lo = pack_hi(a - __bfloat162float(ah), b - __bfloat162float(bh));
}

// C[128x128(+)] += A[128xK]@W ; warp computes 32x64 tile. nks ksteps of 16.
__device__ __forceinline__ void gemm_run(uint32_t aH, uint32_t aL, uint32_t strideA,
                                         int nks, const uint2* __restrict__ Bh,
                                         const uint2* __restrict__ Bl,
                                         int tbase, int jbase, int lane,
                                         float (&acc)[2][8][4]) {
  uint32_t off0 = (lane & 15) * strideA + (lane >> 4) * 16;
  for (int ks = 0; ks < nks; ks++) {
    uint32_t a0h[4], a1h[4], a0l[4], a1l[4];
    uint32_t o = off0 + ks * 32;
    ldm4(a0h, aH + o);
    ldm4(a1h, aH + o + 16 * strideA);
    ldm4(a0l, aL + o);
    ldm4(a1l, aL + o + 16 * strideA);
    const uint2* bh = Bh + ((tbase + ks) * 16 + jbase) * 32 + lane;
    const uint2* bl = Bl + ((tbase + ks) * 16 + jbase) * 32 + lane;
#pragma unroll
    for (int j = 0; j < 8; j++) {
      uint2 BH = bh[j * 32];
      uint2 BL = bl[j * 32];
      mma16816(acc[0][j], a0h, BH);
      mma16816(acc[1][j], a1h, BH);
      mma16816(acc[0][j], a0l, BH);
      mma16816(acc[1][j], a1l, BH);
      mma16816(acc[0][j], a0h, BL);
      mma16816(acc[1][j], a1h, BL);
    }
  }
}

__device__ __forceinline__ void zero_acc(float (&acc)[2][8][4]) {
#pragma unroll
  for (int m = 0; m < 2; m++)
#pragma unroll
    for (int j = 0; j < 8; j++)
#pragma unroll
      for (int q = 0; q < 4; q++) acc[m][j][q] = 0.f;
}

// ---------------------------------------------------------------------------
__global__ void egnn_zero_kernel(int N) {
  long long total = (long long)N * 131;
  long long stride = (long long)gridDim.x * blockDim.x;
  long long n128 = (long long)N * 128;
  for (long long i = (long long)blockIdx.x * blockDim.x + threadIdx.x; i < total; i += stride) {
    if (i < n128) g_agg[i] = 0.f;
    else g_coordU[i - n128] = 0.f;
  }
}

__global__ void egnn_prep_kernel(const float* __restrict__ We1, const float* __restrict__ We2,
                                 const float* __restrict__ Wc1, const float* __restrict__ Wn1,
                                 const float* __restrict__ Wn2) {
  int idx = blockIdx.x * blockDim.x + threadIdx.x;
  if (idx < WB_TOTAL) {
    const float* W;
    int local;
    if (idx < WB_WE2)      { W = We1; local = idx; }
    else if (idx < WB_WC1) { W = We2; local = idx - WB_WE2; }
    else if (idx < WB_WN1) { W = Wc1; local = idx - WB_WC1; }
    else if (idx < WB_WN2) { W = Wn1; local = idx - WB_WN1; }
    else                   { W = Wn2; local = idx - WB_WN2; }
    int r = local & 1;
    int l = (local >> 1) & 31;
    int j = (local >> 6) & 15;
    int t = local >> 10;
    int k = t * 16 + ((l & 3) << 1) + r * 8;
    int n = j * 8 + (l >> 2);
    float w0 = W[k * 128 + n];
    float w1 = W[(k + 1) * 128 + n];
    __nv_bfloat16 h0 = __float2bfloat16_rn(w0), h1 = __float2bfloat16_rn(w1);
    g_Bh[idx] = (uint32_t)__bfloat16_as_ushort(h0) | ((uint32_t)__bfloat16_as_ushort(h1) << 16);
    g_Bl[idx] = pack_hi(w0 - __bfloat162float(h0), w1 - __bfloat162float(h1));
  } else if (idx < WB_TOTAL + 128) {
    g_w256[idx - WB_TOTAL] = We1[256 * 128 + (idx - WB_TOTAL)];
  }
}

// ---------------------------------------------------------------------------
// smem layout (bytes):
//  bufA_h @0       128 x 72 bf16 (stride 144 B)  = 18432
//  bufA_l @18432                                 = 18432
//  bufH_h @36864   128 x 136 bf16 (stride 272 B) = 34816
//  bufH_l @71680                                 = 34816
//  extras @106496
#define OFF_AH 0
#define OFF_AL 18432
#define OFF_HH 36864
#define OFF_HL 71680
#define OFF_EXT 106496
#define STRA 144
#define STRH 272
#define EDGE_SMEM (OFF_EXT + 3584)
#define NODE_SMEM (OFF_EXT)

__global__ void __launch_bounds__(256, 2)
egnn_edge_mma(const float* __restrict__ h, const float* __restrict__ coords,
              const void* __restrict__ eidx_raw,
              const float* __restrict__ be1, const float* __restrict__ be2,
              const float* __restrict__ bc1, const float* __restrict__ Wc2,
              int N, long long E) {
  extern __shared__ char sm[];
  uint32_t sbase = smem_u32(sm);
  float* sRel  = (float*)(sm + OFF_EXT);
  float* sDist = (float*)(sm + OFF_EXT + 1536);
  float* sCW   = (float*)(sm + OFF_EXT + 2048);
  int*   sRow  = (int*)(sm + OFF_EXT + 2560);
  int*   sCol  = (int*)(sm + OFF_EXT + 3072);

  int tid = threadIdx.x, wid = tid >> 5, lane = tid & 31;
  int mrow = (wid >> 1) * 32, jbase = (wid & 1) * 8;
  long long e0 = (long long)blockIdx.x * 128;

  if (tid < 128) {
    sCW[tid] = 0.f;
    long long e = e0 + tid;
    int r = -1, c = 0;
    float rx = 0.f, ry = 0.f, rz = 0.f;
    if (e < E) {
      const unsigned* w = (const unsigned*)eidx_raw;
      bool is64 = (w[1] == 0u && w[3] == 0u && w[5] == 0u && w[7] == 0u);
      if (is64) {
        r = (int)((const long long*)eidx_raw)[e];
        c = (int)((const long long*)eidx_raw)[E + e];
      } else {
        r = ((const int*)eidx_raw)[e];
        c = ((const int*)eidx_raw)[E + e];
      }
      rx = coords[(long long)r * 3 + 0] - coords[(long long)c * 3 + 0];
      ry = coords[(long long)r * 3 + 1] - coords[(long long)c * 3 + 1];
      rz = coords[(long long)r * 3 + 2] - coords[(long long)c * 3 + 2];
    }
    sRow[tid] = r; sCol[tid] = c;
    sRel[tid * 3 + 0] = rx; sRel[tid * 3 + 1] = ry; sRel[tid * 3 + 2] = rz;
    sDist[tid] = rx * rx + ry * ry + rz * rz;
  }
  __syncthreads();

  float acc[2][8][4];
  zero_acc(acc);
  uint32_t aHw = sbase + OFF_AH + mrow * STRA;
  uint32_t aLw = sbase + OFF_AL + mrow * STRA;
  uint32_t hHw = sbase + OFF_HH + mrow * STRH;
  uint32_t hLw = sbase + OFF_HL + mrow * STRH;
  const uint2* Bh;
  const uint2* Bl;

  // ---- GEMM1: hidden = relu([h[row]|h[col]] @ We1 + be1 + d2*w256) ----
  for (int ch = 0; ch < 4; ch++) {
    {
      int r2 = tid >> 1, half = tid & 1;
      int rv = sRow[r2];
      int node = (ch < 2) ? rv : sCol[r2];
      int colbase = (ch & 1) * 64;
      const float* src = h + (long long)node * 128 + colbase + half * 32;
      char* dh = sm + OFF_AH + r2 * STRA + half * 64;
      char* dl = sm + OFF_AL + r2 * STRA + half * 64;
#pragma unroll
      for (int j = 0; j < 8; j++) {
        float4 v = make_float4(0.f, 0.f, 0.f, 0.f);
        if (rv >= 0) v = *(const float4*)(src + j * 4);
        uint32_t h0, l0, h1, l1;
        split2(v.x, v.y, h0, l0);
        split2(v.z, v.w, h1, l1);
        *(uint2*)(dh + j * 8) = make_uint2(h0, h1);
        *(uint2*)(dl + j * 8) = make_uint2(l0, l1);
      }
    }
    __syncthreads();
    Bh = (const uint2*)(g_Bh + WB_WE1);
    Bl = (const uint2*)(g_Bl + WB_WE1);
    gemm_run(aHw, aLw, STRA, 4, Bh, Bl, ch * 4, jbase, lane, acc);
    __syncthreads();
  }
  // epilogue 1 -> bufH (hi/lo split of relu output)
#pragma unroll
  for (int mt = 0; mt < 2; mt++) {
#pragma unroll
    for (int j = 0; j < 8; j++) {
      int col0 = jbase * 8 + j * 8 + (lane & 3) * 2;
      int r0 = mrow + mt * 16 + (lane >> 2), r1 = r0 + 8;
      float b0 = be1[col0], b1 = be1[col0 + 1];
      float w0 = g_w256[col0], w1 = g_w256[col0 + 1];
      float d0 = sDist[r0], d1 = sDist[r1];
      float v00 = fmaxf(acc[mt][j][0] + b0 + d0 * w0, 0.f);
      float v01 = fmaxf(acc[mt][j][1] + b1 + d0 * w1, 0.f);
      float v10 = fmaxf(acc[mt][j][2] + b0 + d1 * w0, 0.f);
      float v11 = fmaxf(acc[mt][j][3] + b1 + d1 * w1, 0.f);
      uint32_t hh, ll;
      split2(v00, v01, hh, ll);
      *(uint32_t*)(sm + OFF_HH + r0 * STRH + col0 * 2) = hh;
      *(uint32_t*)(sm + OFF_HL + r0 * STRH + col0 * 2) = ll;
      split2(v10, v11, hh, ll);
      *(uint32_t*)(sm + OFF_HH + r1 * STRH + col0 * 2) = hh;
      *(uint32_t*)(sm + OFF_HL + r1 * STRH + col0 * 2) = ll;
    }
  }
  __syncthreads();

  // ---- GEMM2: messages = hidden @ We2 + be2 ----
  zero_acc(acc);
  Bh = (const uint2*)(g_Bh + WB_WE2);
  Bl = (const uint2*)(g_Bl + WB_WE2);
  gemm_run(hHw, hLw, STRH, 8, Bh, Bl, 0, jbase, lane, acc);
  // scatter agg (before overwriting bufH), add bias into acc
#pragma unroll
  for (int mt = 0; mt < 2; mt++) {
#pragma unroll
    for (int j = 0; j < 8; j++) {
      int col0 = jbase * 8 + j * 8 + (lane & 3) * 2;
      int r0 = mrow + mt * 16 + (lane >> 2), r1 = r0 + 8;
      float b0 = be2[col0], b1 = be2[col0 + 1];
      acc[mt][j][0] += b0; acc[mt][j][1] += b1;
      acc[mt][j][2] += b0; acc[mt][j][3] += b1;
      int n0 = sRow[r0], n1 = sRow[r1];
      if (n0 >= 0) red_v2(&g_agg[(long long)n0 * 128 + col0], acc[mt][j][0], acc[mt][j][1]);
      if (n1 >= 0) red_v2(&g_agg[(long long)n1 * 128 + col0], acc[mt][j][2], acc[mt][j][3]);
    }
  }
  __syncthreads();
  // store messages (split) into bufH for GEMM3
#pragma unroll
  for (int mt = 0; mt < 2; mt++) {
#pragma unroll
    for (int j = 0; j < 8; j++) {
      int col0 = jbase * 8 + j * 8 + (lane & 3) * 2;
      int r0 = mrow + mt * 16 + (lane >> 2), r1 = r0 + 8;
      uint32_t hh, ll;
      split2(acc[mt][j][0], acc[mt][j][1], hh, ll);
      *(uint32_t*)(sm + OFF_HH + r0 * STRH + col0 * 2) = hh;
      *(uint32_t*)(sm + OFF_HL + r0 * STRH + col0 * 2) = ll;
      split2(acc[mt][j][2], acc[mt][j][3], hh, ll);
      *(uint32_t*)(sm + OFF_HH + r1 * STRH + col0 * 2) = hh;
      *(uint32_t*)(sm + OFF_HL + r1 * STRH + col0 * 2) = ll;
    }
  }
  __syncthreads();

  // ---- GEMM3: t2 = relu(messages @ Wc1 + bc1); cw = t2 @ Wc2 ----
  zero_acc(acc);
  Bh = (const uint2*)(g_Bh + WB_WC1);
  Bl = (const uint2*)(g_Bl + WB_WC1);
  gemm_run(hHw, hLw, STRH, 8, Bh, Bl, 0, jbase, lane, acc);
  {
    float p[2][2] = {{0.f, 0.f}, {0.f, 0.f}};
#pragma unroll
    for (int mt = 0; mt < 2; mt++) {
#pragma unroll
      for (int j = 0; j < 8; j++) {
        int col0 = jbase * 8 + j * 8 + (lane & 3) * 2;
        float b0 = bc1[col0], b1 = bc1[col0 + 1];
        float w0 = Wc2[col0], w1 = Wc2[col0 + 1];
        p[mt][0] += fmaxf(acc[mt][j][0] + b0, 0.f) * w0 + fmaxf(acc[mt][j][1] + b1, 0.f) * w1;
        p[mt][1] += fmaxf(acc[mt][j][2] + b0, 0.f) * w0 + fmaxf(acc[mt][j][3] + b1, 0.f) * w1;
      }
    }
#pragma unroll
    for (int mt = 0; mt < 2; mt++)
#pragma unroll
      for (int q = 0; q < 2; q++) {
        p[mt][q] += __shfl_xor_sync(0xffffffffu, p[mt][q], 1);
        p[mt][q] += __shfl_xor_sync(0xffffffffu, p[mt][q], 2);
      }
    if ((lane & 3) == 0) {
      int r0 = mrow + (lane >> 2);
      atomicAdd(&sCW[r0], p[0][0]);
      atomicAdd(&sCW[r0 + 8], p[0][1]);
      atomicAdd(&sCW[r0 + 16], p[1][0]);
      atomicAdd(&sCW[r0 + 24], p[1][1]);
    }
  }
  __syncthreads();
  for (int i = tid; i < 384; i += 256) {
    int le = i / 3, a = i - le * 3;
    int node = sRow[le];
    if (node >= 0)
      atomicAdd(&g_coordU[(long long)node * 3 + a], sCW[le] * sRel[le * 3 + a]);
  }
}

__global__ void __launch_bounds__(256, 2)
egnn_node_mma(const float* __restrict__ h, const float* __restrict__ coords,
              const float* __restrict__ bn1, const float* __restrict__ bn2,
              float* __restrict__ out, int N) {
  extern __shared__ char sm[];
  uint32_t sbase = smem_u32(sm);
  int tid = threadIdx.x, wid = tid >> 5, lane = tid & 31;
  int mrow = (wid >> 1) * 32, jbase = (wid & 1) * 8;
  int n0 = blockIdx.x * 128;

  float acc[2][8][4];
  zero_acc(acc);
  uint32_t aHw = sbase + OFF_AH + mrow * STRA;
  uint32_t aLw = sbase + OFF_AL + mrow * STRA;
  uint32_t hHw = sbase + OFF_HH + mrow * STRH;
  uint32_t hLw = sbase + OFF_HL + mrow * STRH;
  const uint2* Bh;
  const uint2* Bl;

  // GEMM1: hid = relu([h|agg] @ Wn1 + bn1)
  for (int ch = 0; ch < 4; ch++) {
    {
      int r2 = tid >> 1, half = tid & 1;
      int node = n0 + r2;
      bool ok = node < N;
      int colbase = (ch & 1) * 64;
      const float* base = (ch < 2) ? h : g_agg;
      const float* src = base + (long long)node * 128 + colbase + half * 32;
      char* dh = sm + OFF_AH + r2 * STRA + half * 64;
      char* dl = sm + OFF_AL + r2 * STRA + half * 64;
#pragma unroll
      for (int j = 0; j < 8; j++) {
        float4 v = make_float4(0.f, 0.f, 0.f, 0.f);
        if (ok) v = *(const float4*)(src + j * 4);
        uint32_t h0, l0, h1, l1;
        split2(v.x, v.y, h0, l0);
        split2(v.z, v.w, h1, l1);
        *(uint2*)(dh + j * 8) = make_uint2(h0, h1);
        *(uint2*)(dl + j * 8) = make_uint2(l0, l1);
      }
    }
    __syncthreads();
    Bh = (const uint2*)(g_Bh + WB_WN1);
    Bl = (const uint2*)(g_Bl + WB_WN1);
    gemm_run(aHw, aLw, STRA, 4, Bh, Bl, ch * 4, jbase, lane, acc);
    __syncthreads();
  }
#pragma unroll
  for (int mt = 0; mt < 2; mt++) {
#pragma unroll
    for (int j = 0; j < 8; j++) {
      int col0 = jbase * 8 + j * 8 + (lane & 3) * 2;
      int r0 = mrow + mt * 16 + (lane >> 2), r1 = r0 + 8;
      float b0 = bn1[col0], b1 = bn1[col0 + 1];
      float v00 = fmaxf(acc[mt][j][0] + b0, 0.f);
      float v01 = fmaxf(acc[mt][j][1] + b1, 0.f);
      float v10 = fmaxf(acc[mt][j][2] + b0, 0.f);
      float v11 = fmaxf(acc[mt][j][3] + b1, 0.f);
      uint32_t hh, ll;
      split2(v00, v01, hh, ll);
      *(uint32_t*)(sm + OFF_HH + r0 * STRH + col0 * 2) = hh;
      *(uint32_t*)(sm + OFF_HL + r0 * STRH + col0 * 2) = ll;
      split2(v10, v11, hh, ll);
      *(uint32_t*)(sm + OFF_HH + r1 * STRH + col0 * 2) = hh;
      *(uint32_t*)(sm + OFF_HL + r1 * STRH + col0 * 2) = ll;
    }
  }
  __syncthreads();

  // GEMM2: h_new = hid @ Wn2 + bn2
  zero_acc(acc);
  Bh = (const uint2*)(g_Bh + WB_WN2);
  Bl = (const uint2*)(g_Bl + WB_WN2);
  gemm_run(hHw, hLw, STRH, 8, Bh, Bl, 0, jbase, lane, acc);
#pragma unroll
  for (int mt = 0; mt < 2; mt++) {
#pragma unroll
    for (int j = 0; j < 8; j++) {
      int col0 = jbase * 8 + j * 8 + (lane & 3) * 2;
      int r0 = mrow + mt * 16 + (lane >> 2), r1 = r0 + 8;
      float b0 = bn2[col0], b1 = bn2[col0 + 1];
      int node0 = n0 + r0, node1 = n0 + r1;
      if (node0 < N) {
        float2 v = make_float2(acc[mt][j][0] + b0, acc[mt][j][1] + b1);
        *(float2*)&out[(long long)node0 * 128 + col0] = v;
      }
      if (node1 < N) {
        float2 v = make_float2(acc[mt][j][2] + b0, acc[mt][j][3] + b1);
        *(float2*)&out[(long long)node1 * 128 + col0] = v;
      }
    }
  }
  for (int i = tid; i < 384; i += 256) {
    int ln = i / 3, a = i - ln * 3;
    int node = n0 + ln;
    if (node < N)
      out[(long long)N * 128 + (long long)node * 3 + a] =
          coords[(long long)node * 3 + a] + g_coordU[(long long)node * 3 + a];
  }
}

// ---------------------------------------------------------------------------
extern "C" void kernel_launch(void* const* d_in, const int* in_sizes, int n_in,
                              void* d_out, int out_size) {
  const float* h      = (const float*)d_in[0];
  const float* coords = (const float*)d_in[1];
  const void*  eidx   = d_in[2];
  const float* We1 = (const float*)d_in[3];
  const float* be1 = (const float*)d_in[4];
  const float* We2 = (const float*)d_in[5];
  const float* be2 = (const float*)d_in[6];
  const float* Wn1 = (const float*)d_in[7];
  const float* bn1 = (const float*)d_in[8];
  const float* Wn2 = (const float*)d_in[9];
  const float* bn2 = (const float*)d_in[10];
  const float* Wc1 = (const float*)d_in[11];
  const float* bc1 = (const float*)d_in[12];
  const float* Wc2 = (const float*)d_in[13];

  int N = in_sizes[0] / 128;
  long long E = (long long)in_sizes[2] / 2;

  cudaFuncSetAttribute(egnn_edge_mma, cudaFuncAttributeMaxDynamicSharedMemorySize, EDGE_SMEM);
  cudaFuncSetAttribute(egnn_node_mma, cudaFuncAttributeMaxDynamicSharedMemorySize, NODE_SMEM);

  egnn_zero_kernel<<<432, 256>>>(N);
  egnn_prep_kernel<<<(WB_TOTAL + 128 + 255) / 256, 256>>>(We1, We2, Wc1, Wn1, Wn2);

  int egrid = (int)((E + 127) / 128);
  egnn_edge_mma<<<egrid, 256, EDGE_SMEM>>>(h, coords, eidx, be1, be2, bc1, Wc2, N, E);

  int ngrid = (N + 127) / 128;
  egnn_node_mma<<<ngrid, 256, NODE_SMEM>>>(h, coords, bn1, bn2, (float*)d_out, N);
}

// round 4
// speedup vs baseline: 3.6019x; 1.0407x over previous
#include <cuda_runtime.h>
#include <cuda_bf16.h>
#include <cstdint>

// ============================================================================
// EGNN decoder layer — warp-level HMMA (mma.sync m16n8k16 bf16) with
// split-precision (X = Xhi + Xlo; X@W ~= Xhi@Whi + Xhi@Wlo + Xlo@Whi, fp32 acc).
// Round 4: cp.async pipelined gather, raw-fp32 smem A with in-register hi/lo
// fragment split, uint4-packed B fragments (one LDG.128 per n8 tile).
// ============================================================================

#define MAXN 50000
static __device__ float g_agg[MAXN * 128];
static __device__ float g_coordU[MAXN * 3];

// B fragment images packed as uint4 {hi_k0, hi_k8, lo_k0, lo_k8} per
// (kstep t, n8-tile j, lane): index = (t*16 + j)*32 + lane.
#define W4_WE1 0        // K=256 -> 8192 uint4
#define W4_WE2 8192     // K=128 -> 4096
#define W4_WC1 12288    //          4096
#define W4_WN1 16384    // K=256 -> 8192
#define W4_WN2 24576    //          4096
#define W4_TOTAL 28672
static __device__ __align__(16) uint4 g_B[W4_TOTAL];
static __device__ float g_w256[128];  // dist2 row (row 256) of We1

// smem geometry (bytes). Staging (2 x 128x68 fp32) aliases bufH (128x136 fp32):
// staging dead after GEMM1's last MMA; bufH written in epilogue1 after a sync.
#define STR_S 272
#define STR_H 544
#define STG0 0
#define STG1 34816
#define H_OFF 0
#define EXT_OFF 69632
#define EDGE_SMEM (EXT_OFF + 3584)
#define NODE_SMEM (EXT_OFF)

// ---------------------------------------------------------------------------
__device__ __forceinline__ uint32_t smem_u32(const void* p) {
  uint32_t a;
  asm("{ .reg .u64 t; cvta.to.shared.u64 t, %1; cvt.u32.u64 %0, t; }"
      : "=r"(a) : "l"(p));
  return a;
}

__device__ __forceinline__ void mma16816(float* c, const uint32_t* a, uint2 b) {
  asm volatile(
      "mma.sync.aligned.m16n8k16.row.col.f32.bf16.bf16.f32 "
      "{%0,%1,%2,%3}, {%4,%5,%6,%7}, {%8,%9}, {%0,%1,%2,%3};"
      : "+f"(c[0]), "+f"(c[1]), "+f"(c[2]), "+f"(c[3])
      : "r"(a[0]), "r"(a[1]), "r"(a[2]), "r"(a[3]), "r"(b.x), "r"(b.y));
}

__device__ __forceinline__ void red_v2(float* g, float x, float y) {
  asm volatile("red.global.add.v2.f32 [%0], {%1,%2};"
               :: "l"(g), "f"(x), "f"(y) : "memory");
}

#define CP_ASYNC16(dst, src) \
  asm volatile("cp.async.cg.shared.global [%0], [%1], 16;" :: "r"(dst), "l"(src) : "memory")
#define CP_COMMIT() asm volatile("cp.async.commit_group;" ::: "memory")
#define CP_WAIT(n)  asm volatile("cp.async.wait_group %0;" :: "n"(n) : "memory")

__device__ __forceinline__ uint32_t pack_bf2(float a, float b) {
  __nv_bfloat16 x = __float2bfloat16_rn(a), y = __float2bfloat16_rn(b);
  return (uint32_t)__bfloat16_as_ushort(x) | ((uint32_t)__bfloat16_as_ushort(y) << 16);
}
__device__ __forceinline__ void split2f(float2 p, uint32_t& hi, uint32_t& lo) {
  __nv_bfloat16 ah = __float2bfloat16_rn(p.x), bh = __float2bfloat16_rn(p.y);
  hi = (uint32_t)__bfloat16_as_ushort(ah) | ((uint32_t)__bfloat16_as_ushort(bh) << 16);
  lo = pack_bf2(p.x - __bfloat162float(ah), p.y - __bfloat162float(bh));
}

__device__ __forceinline__ void zero_acc(float (&acc)[2][8][4]) {
#pragma unroll
  for (int m = 0; m < 2; m++)
#pragma unroll
    for (int j = 0; j < 8; j++)
#pragma unroll
      for (int q = 0; q < 4; q++) acc[m][j][q] = 0.f;
}

// C[128x128] += A[128x(NKS*16)] @ W. A is raw fp32 in smem (stride strideB);
// hi/lo bf16 fragments built in registers. Warp computes rows mrow..+31,
// n8-tiles jbase..jbase+7.
template <int NKS>
__device__ __forceinline__ void gemm_raw(const char* __restrict__ sm, uint32_t aOff,
                                         uint32_t strideB, const uint4* __restrict__ Bp,
                                         int tbase, int jbase, int mrow, int lane,
                                         float (&acc)[2][8][4]) {
  int g = lane >> 2, c2 = (lane & 3) * 2;
  uint32_t base0 = aOff + (uint32_t)(mrow + g) * strideB + (uint32_t)c2 * 4;
#pragma unroll
  for (int ks = 0; ks < NKS; ks++) {
    uint32_t aH[2][4], aL[2][4];
#pragma unroll
    for (int mt = 0; mt < 2; mt++) {
      uint32_t o = base0 + (uint32_t)mt * 16 * strideB + (uint32_t)ks * 64;
      float2 p0 = *(const float2*)(sm + o);
      float2 p1 = *(const float2*)(sm + o + 8 * strideB);
      float2 p2 = *(const float2*)(sm + o + 32);
      float2 p3 = *(const float2*)(sm + o + 8 * strideB + 32);
      split2f(p0, aH[mt][0], aL[mt][0]);
      split2f(p1, aH[mt][1], aL[mt][1]);
      split2f(p2, aH[mt][2], aL[mt][2]);
      split2f(p3, aH[mt][3], aL[mt][3]);
    }
    const uint4* bp = Bp + ((tbase + ks) * 16 + jbase) * 32 + lane;
#pragma unroll
    for (int j = 0; j < 8; j++) {
      uint4 B = bp[j * 32];
      uint2 BH = make_uint2(B.x, B.y), BL = make_uint2(B.z, B.w);
      mma16816(acc[0][j], aH[0], BH);
      mma16816(acc[1][j], aH[1], BH);
      mma16816(acc[0][j], aL[0], BH);
      mma16816(acc[1][j], aL[1], BH);
      mma16816(acc[0][j], aH[0], BL);
      mma16816(acc[1][j], aH[1], BL);
    }
  }
}

// ---------------------------------------------------------------------------
__global__ void egnn_zero_kernel(int N) {
  long long total = (long long)N * 131;
  long long stride = (long long)gridDim.x * blockDim.x;
  long long n128 = (long long)N * 128;
  for (long long i = (long long)blockIdx.x * blockDim.x + threadIdx.x; i < total; i += stride) {
    if (i < n128) g_agg[i] = 0.f;
    else g_coordU[i - n128] = 0.f;
  }
}

__global__ void egnn_prep_kernel(const float* __restrict__ We1, const float* __restrict__ We2,
                                 const float* __restrict__ Wc1, const float* __restrict__ Wn1,
                                 const float* __restrict__ Wn2) {
  int idx = blockIdx.x * blockDim.x + threadIdx.x;
  if (idx < W4_TOTAL) {
    const float* W;
    int local;
    if (idx < W4_WE2)      { W = We1; local = idx; }
    else if (idx < W4_WC1) { W = We2; local = idx - W4_WE2; }
    else if (idx < W4_WN1) { W = Wc1; local = idx - W4_WC1; }
    else if (idx < W4_WN2) { W = Wn1; local = idx - W4_WN1; }
    else                   { W = Wn2; local = idx - W4_WN2; }
    int l = local & 31;
    int j = (local >> 5) & 15;
    int t = local >> 9;
    int k0 = t * 16 + ((l & 3) << 1);
    int n = j * 8 + (l >> 2);
    float w00 = W[k0 * 128 + n],       w01 = W[(k0 + 1) * 128 + n];
    float w10 = W[(k0 + 8) * 128 + n], w11 = W[(k0 + 9) * 128 + n];
    __nv_bfloat16 h00 = __float2bfloat16_rn(w00), h01 = __float2bfloat16_rn(w01);
    __nv_bfloat16 h10 = __float2bfloat16_rn(w10), h11 = __float2bfloat16_rn(w11);
    uint4 v;
    v.x = (uint32_t)__bfloat16_as_ushort(h00) | ((uint32_t)__bfloat16_as_ushort(h01) << 16);
    v.y = (uint32_t)__bfloat16_as_ushort(h10) | ((uint32_t)__bfloat16_as_ushort(h11) << 16);
    v.z = pack_bf2(w00 - __bfloat162float(h00), w01 - __bfloat162float(h01));
    v.w = pack_bf2(w10 - __bfloat162float(h10), w11 - __bfloat162float(h11));
    g_B[idx] = v;
  } else if (idx < W4_TOTAL + 128) {
    g_w256[idx - W4_TOTAL] = We1[256 * 128 + (idx - W4_TOTAL)];
  }
}

// ---------------------------------------------------------------------------
__device__ __forceinline__ void edge_issue(const float* __restrict__ h,
                                           const int* __restrict__ sRow,
                                           const int* __restrict__ sCol,
                                           uint32_t dstBase, int ch, int tid) {
  int r2 = tid >> 1, half = tid & 1;
  int rv = (ch < 2) ? sRow[r2] : sCol[r2];
  int node = rv < 0 ? 0 : rv;
  const float* src = h + (long long)node * 128 + (ch & 1) * 64 + half * 32;
  uint32_t dst = dstBase + (uint32_t)r2 * STR_S + (uint32_t)half * 128;
#pragma unroll
  for (int j = 0; j < 8; j++) CP_ASYNC16(dst + j * 16, src + j * 4);
}

__global__ void __launch_bounds__(256, 2)
egnn_edge_mma(const float* __restrict__ h, const float* __restrict__ coords,
              const void* __restrict__ eidx_raw,
              const float* __restrict__ be1, const float* __restrict__ be2,
              const float* __restrict__ bc1, const float* __restrict__ Wc2,
              int N, long long E) {
  extern __shared__ char sm[];
  uint32_t sb = smem_u32(sm);
  float* sRel  = (float*)(sm + EXT_OFF);
  float* sDist = (float*)(sm + EXT_OFF + 1536);
  float* sCW   = (float*)(sm + EXT_OFF + 2048);
  int*   sRow  = (int*)(sm + EXT_OFF + 2560);
  int*   sCol  = (int*)(sm + EXT_OFF + 3072);

  int tid = threadIdx.x, wid = tid >> 5, lane = tid & 31;
  int mrow = (wid >> 1) * 32, jbase = (wid & 1) * 8;
  int c2 = (lane & 3) * 2, g = lane >> 2;
  long long e0 = (long long)blockIdx.x * 128;

  if (tid < 128) {
    sCW[tid] = 0.f;
    long long e = e0 + tid;
    int r = -1, c = 0;
    float rx = 0.f, ry = 0.f, rz = 0.f;
    if (e < E) {
      const unsigned* w = (const unsigned*)eidx_raw;
      bool is64 = (w[1] == 0u && w[3] == 0u && w[5] == 0u && w[7] == 0u);
      if (is64) {
        r = (int)((const long long*)eidx_raw)[e];
        c = (int)((const long long*)eidx_raw)[E + e];
      } else {
        r = ((const int*)eidx_raw)[e];
        c = ((const int*)eidx_raw)[E + e];
      }
      rx = coords[(long long)r * 3 + 0] - coords[(long long)c * 3 + 0];
      ry = coords[(long long)r * 3 + 1] - coords[(long long)c * 3 + 1];
      rz = coords[(long long)r * 3 + 2] - coords[(long long)c * 3 + 2];
    }
    sRow[tid] = r; sCol[tid] = c;
    sRel[tid * 3 + 0] = rx; sRel[tid * 3 + 1] = ry; sRel[tid * 3 + 2] = rz;
    sDist[tid] = rx * rx + ry * ry + rz * rz;
  }
  __syncthreads();

  // prime the gather pipeline
  edge_issue(h, sRow, sCol, sb + STG0, 0, tid); CP_COMMIT();
  edge_issue(h, sRow, sCol, sb + STG1, 1, tid); CP_COMMIT();

  float acc[2][8][4];
  zero_acc(acc);

  // ---- GEMM1: hidden = relu([h[row]|h[col]] @ We1 + be1 + d2*w256) ----
#pragma unroll
  for (int ch = 0; ch < 4; ch++) {
    if (ch < 3) { CP_WAIT(1); } else { CP_WAIT(0); }
    __syncthreads();
    gemm_raw<4>(sm, (ch & 1) ? STG1 : STG0, STR_S, g_B + W4_WE1, ch * 4,
                jbase, mrow, lane, acc);
    __syncthreads();
    if (ch < 2) {
      edge_issue(h, sRow, sCol, sb + ((ch & 1) ? STG1 : STG0), ch + 2, tid);
      CP_COMMIT();
    }
  }
  // epilogue 1 -> bufH raw fp32 (aliases staging; safe after syncs above)
#pragma unroll
  for (int mt = 0; mt < 2; mt++) {
#pragma unroll
    for (int j = 0; j < 8; j++) {
      int col0 = (jbase + j) * 8 + c2;
      int r0 = mrow + mt * 16 + g, r1 = r0 + 8;
      float b0 = be1[col0], b1 = be1[col0 + 1];
      float w0 = g_w256[col0], w1 = g_w256[col0 + 1];
      float d0 = sDist[r0], d1 = sDist[r1];
      *(float2*)(sm + H_OFF + r0 * STR_H + col0 * 4) =
          make_float2(fmaxf(acc[mt][j][0] + b0 + d0 * w0, 0.f),
                      fmaxf(acc[mt][j][1] + b1 + d0 * w1, 0.f));
      *(float2*)(sm + H_OFF + r1 * STR_H + col0 * 4) =
          make_float2(fmaxf(acc[mt][j][2] + b0 + d1 * w0, 0.f),
                      fmaxf(acc[mt][j][3] + b1 + d1 * w1, 0.f));
    }
  }
  __syncthreads();

  // ---- GEMM2: messages = hidden @ We2 + be2 ----
  zero_acc(acc);
  gemm_raw<8>(sm, H_OFF, STR_H, g_B + W4_WE2, 0, jbase, mrow, lane, acc);
  // scatter agg (fire-and-forget REDs) with bias folded in
#pragma unroll
  for (int mt = 0; mt < 2; mt++) {
#pragma unroll
    for (int j = 0; j < 8; j++) {
      int col0 = (jbase + j) * 8 + c2;
      int r0 = mrow + mt * 16 + g, r1 = r0 + 8;
      float b0 = be2[col0], b1 = be2[col0 + 1];
      acc[mt][j][0] += b0; acc[mt][j][1] += b1;
      acc[mt][j][2] += b0; acc[mt][j][3] += b1;
      int n0 = sRow[r0], n1 = sRow[r1];
      if (n0 >= 0) red_v2(&g_agg[(long long)n0 * 128 + col0], acc[mt][j][0], acc[mt][j][1]);
      if (n1 >= 0) red_v2(&g_agg[(long long)n1 * 128 + col0], acc[mt][j][2], acc[mt][j][3]);
    }
  }
  __syncthreads();
  // store messages fp32 for GEMM3
#pragma unroll
  for (int mt = 0; mt < 2; mt++) {
#pragma unroll
    for (int j = 0; j < 8; j++) {
      int col0 = (jbase + j) * 8 + c2;
      int r0 = mrow + mt * 16 + g, r1 = r0 + 8;
      *(float2*)(sm + H_OFF + r0 * STR_H + col0 * 4) = make_float2(acc[mt][j][0], acc[mt][j][1]);
      *(float2*)(sm + H_OFF + r1 * STR_H + col0 * 4) = make_float2(acc[mt][j][2], acc[mt][j][3]);
    }
  }
  __syncthreads();

  // ---- GEMM3: t2 = relu(messages @ Wc1 + bc1); cw = t2 @ Wc2 ----
  zero_acc(acc);
  gemm_raw<8>(sm, H_OFF, STR_H, g_B + W4_WC1, 0, jbase, mrow, lane, acc);
  {
    float p[2][2] = {{0.f, 0.f}, {0.f, 0.f}};
#pragma unroll
    for (int mt = 0; mt < 2; mt++) {
#pragma unroll
      for (int j = 0; j < 8; j++) {
        int col0 = (jbase + j) * 8 + c2;
        float b0 = bc1[col0], b1 = bc1[col0 + 1];
        float w0 = Wc2[col0], w1 = Wc2[col0 + 1];
        p[mt][0] += fmaxf(acc[mt][j][0] + b0, 0.f) * w0 + fmaxf(acc[mt][j][1] + b1, 0.f) * w1;
        p[mt][1] += fmaxf(acc[mt][j][2] + b0, 0.f) * w0 + fmaxf(acc[mt][j][3] + b1, 0.f) * w1;
      }
    }
#pragma unroll
    for (int mt = 0; mt < 2; mt++)
#pragma unroll
      for (int q = 0; q < 2; q++) {
        p[mt][q] += __shfl_xor_sync(0xffffffffu, p[mt][q], 1);
        p[mt][q] += __shfl_xor_sync(0xffffffffu, p[mt][q], 2);
      }
    if ((lane & 3) == 0) {
      int r0 = mrow + g;
      atomicAdd(&sCW[r0], p[0][0]);
      atomicAdd(&sCW[r0 + 8], p[0][1]);
      atomicAdd(&sCW[r0 + 16], p[1][0]);
      atomicAdd(&sCW[r0 + 24], p[1][1]);
    }
  }
  __syncthreads();
  for (int i = tid; i < 384; i += 256) {
    int le = i / 3, a = i - le * 3;
    int node = sRow[le];
    if (node >= 0)
      atomicAdd(&g_coordU[(long long)node * 3 + a], sCW[le] * sRel[le * 3 + a]);
  }
}

// ---------------------------------------------------------------------------
__device__ __forceinline__ void node_issue(const float* __restrict__ h,
                                           uint32_t dstBase, int ch, int tid,
                                           int n0, int Nn) {
  int r2 = tid >> 1, half = tid & 1;
  int node = n0 + r2;
  if (node >= Nn) node = Nn - 1;
  const float* src = h + (long long)node * 128 + (ch & 1) * 64 + half * 32;
  uint32_t dst = dstBase + (uint32_t)r2 * STR_S + (uint32_t)half * 128;
#pragma unroll
  for (int j = 0; j < 8; j++) CP_ASYNC16(dst + j * 16, src + j * 4);
}

__global__ void __launch_bounds__(256, 2)
egnn_node_mma(const float* __restrict__ h, const float* __restrict__ coords,
              const float* __restrict__ bn1, const float* __restrict__ bn2,
              float* __restrict__ out, int N) {
  extern __shared__ char sm[];
  uint32_t sb = smem_u32(sm);
  int tid = threadIdx.x, wid = tid >> 5, lane = tid & 31;
  int mrow = (wid >> 1) * 32, jbase = (wid & 1) * 8;
  int c2 = (lane & 3) * 2, g = lane >> 2;
  int n0 = blockIdx.x * 128;

  node_issue(h, sb + STG0, 0, tid, n0, N); CP_COMMIT();
  node_issue(h, sb + STG1, 1, tid, n0, N); CP_COMMIT();

  float acc[2][8][4];
  zero_acc(acc);

  // GEMM1: hid = relu([h|agg] @ Wn1 + bn1)
#pragma unroll
  for (int ch = 0; ch < 4; ch++) {
    if (ch < 3) { CP_WAIT(1); } else { CP_WAIT(0); }
    __syncthreads();
    gemm_raw<4>(sm, (ch & 1) ? STG1 : STG0, STR_S, g_B + W4_WN1, ch * 4,
                jbase, mrow, lane, acc);
    __syncthreads();
    if (ch < 2) {
      node_issue(g_agg, sb + ((ch & 1) ? STG1 : STG0), ch + 2, tid, n0, N);
      CP_COMMIT();
    }
  }
#pragma unroll
  for (int mt = 0; mt < 2; mt++) {
#pragma unroll
    for (int j = 0; j < 8; j++) {
      int col0 = (jbase + j) * 8 + c2;
      int r0 = mrow + mt * 16 + g, r1 = r0 + 8;
      float b0 = bn1[col0], b1 = bn1[col0 + 1];
      *(float2*)(sm + H_OFF + r0 * STR_H + col0 * 4) =
          make_float2(fmaxf(acc[mt][j][0] + b0, 0.f), fmaxf(acc[mt][j][1] + b1, 0.f));
      *(float2*)(sm + H_OFF + r1 * STR_H + col0 * 4) =
          make_float2(fmaxf(acc[mt][j][2] + b0, 0.f), fmaxf(acc[mt][j][3] + b1, 0.f));
    }
  }
  __syncthreads();

  // GEMM2: h_new = hid @ Wn2 + bn2
  zero_acc(acc);
  gemm_raw<8>(sm, H_OFF, STR_H, g_B + W4_WN2, 0, jbase, mrow, lane, acc);
#pragma unroll
  for (int mt = 0; mt < 2; mt++) {
#pragma unroll
    for (int j = 0; j < 8; j++) {
      int col0 = (jbase + j) * 8 + c2;
      int r0 = mrow + mt * 16 + g, r1 = r0 + 8;
      float b0 = bn2[col0], b1 = bn2[col0 + 1];
      int node0 = n0 + r0, node1 = n0 + r1;
      if (node0 < N)
        *(float2*)&out[(long long)node0 * 128 + col0] =
            make_float2(acc[mt][j][0] + b0, acc[mt][j][1] + b1);
      if (node1 < N)
        *(float2*)&out[(long long)node1 * 128 + col0] =
            make_float2(acc[mt][j][2] + b0, acc[mt][j][3] + b1);
    }
  }
  for (int i = tid; i < 384; i += 256) {
    int ln = i / 3, a = i - ln * 3;
    int node = n0 + ln;
    if (node < N)
      out[(long long)N * 128 + (long long)node * 3 + a] =
          coords[(long long)node * 3 + a] + g_coordU[(long long)node * 3 + a];
  }
}

// ---------------------------------------------------------------------------
extern "C" void kernel_launch(void* const* d_in, const int* in_sizes, int n_in,
                              void* d_out, int out_size) {
  const float* h      = (const float*)d_in[0];
  const float* coords = (const float*)d_in[1];
  const void*  eidx   = d_in[2];
  const float* We1 = (const float*)d_in[3];
  const float* be1 = (const float*)d_in[4];
  const float* We2 = (const float*)d_in[5];
  const float* be2 = (const float*)d_in[6];
  const float* Wn1 = (const float*)d_in[7];
  const float* bn1 = (const float*)d_in[8];
  const float* Wn2 = (const float*)d_in[9];
  const float* bn2 = (const float*)d_in[10];
  const float* Wc1 = (const float*)d_in[11];
  const float* bc1 = (const float*)d_in[12];
  const float* Wc2 = (const float*)d_in[13];

  int N = in_sizes[0] / 128;
  long long E = (long long)in_sizes[2] / 2;

  cudaFuncSetAttribute(egnn_edge_mma, cudaFuncAttributeMaxDynamicSharedMemorySize, EDGE_SMEM);
  cudaFuncSetAttribute(egnn_node_mma, cudaFuncAttributeMaxDynamicSharedMemorySize, NODE_SMEM);

  egnn_zero_kernel<<<432, 256>>>(N);
  egnn_prep_kernel<<<(W4_TOTAL + 128 + 255) / 256, 256>>>(We1, We2, Wc1, Wn1, Wn2);

  int egrid = (int)((E + 127) / 128);
  egnn_edge_mma<<<egrid, 256, EDGE_SMEM>>>(h, coords, eidx, be1, be2, bc1, Wc2, N, E);

  int ngrid = (N + 127) / 128;
  egnn_node_mma<<<ngrid, 256, NODE_SMEM>>>(h, coords, bn1, bn2, (float*)d_out, N);
}